// round 2
// baseline (speedup 1.0000x reference)
#include <cuda_runtime.h>
#include <math.h>

#define D 128
#define SEGS 32
#define ROWS_PER_BLOCK 128

// Scratch (no allocations allowed) — zeroed every launch by zero_kernel.
__device__ float g_sums[SEGS * D];
__device__ float g_cnt[SEGS];
__device__ float g_gateV[SEGS * D];
__device__ float g_gateE[SEGS * D];

// ---------------------------------------------------------------------------
__global__ void zero_kernel() {
    int i = blockIdx.x * blockDim.x + threadIdx.x;
    if (i < SEGS * D) g_sums[i] = 0.0f;
    if (i < SEGS) g_cnt[i] = 0.0f;
}

// ---------------------------------------------------------------------------
// Segment sums over sorted batch_id. 128 threads/block, one column each.
// Register accumulation; atomic flush only on segment change / block end.
__global__ void seg_sum_kernel(const float* __restrict__ x,
                               const int* __restrict__ bid, int N) {
    int r0 = blockIdx.x * ROWS_PER_BLOCK;
    if (r0 >= N) return;
    int r1 = min(r0 + ROWS_PER_BLOCK, N);
    int t = threadIdx.x;

    float acc = 0.0f;
    float cnt = 0.0f;
    int cur = bid[r0];

    for (int r = r0; r < r1; r++) {
        int s = __ldg(&bid[r]);
        if (s != cur) {
            atomicAdd(&g_sums[cur * D + t], acc);
            if (t == 0) atomicAdd(&g_cnt[cur], cnt);
            acc = 0.0f; cnt = 0.0f; cur = s;
        }
        acc += x[(size_t)r * D + t];
        cnt += 1.0f;
    }
    atomicAdd(&g_sums[cur * D + t], acc);
    if (t == 0) atomicAdd(&g_cnt[cur], cnt);
}

// ---------------------------------------------------------------------------
// Tiny MLPs: 32 blocks (one per segment), 128 threads (one per feature).
// gate_V = sig(mlp_V(c_V)); c_V2 = c_V * gate_V (exact algebraic identity
// since gate is constant per segment and mean is linear); gate_E = sig(mlp_E(c_V2)).
__device__ __forceinline__ float layer_dot(const float* __restrict__ sx,
                                           const float* __restrict__ W,
                                           const float* __restrict__ b, int t) {
    float s = __ldg(&b[t]);
#pragma unroll 16
    for (int k = 0; k < D; k++)
        s = fmaf(sx[k], __ldg(&W[k * D + t]), s);
    return s;
}

__global__ void mlp_kernel(
    const float* __restrict__ VW1, const float* __restrict__ Vb1,
    const float* __restrict__ VW2, const float* __restrict__ Vb2,
    const float* __restrict__ VW3, const float* __restrict__ Vb3,
    const float* __restrict__ EW1, const float* __restrict__ Eb1,
    const float* __restrict__ EW2, const float* __restrict__ Eb2,
    const float* __restrict__ EW3, const float* __restrict__ Eb3) {
    __shared__ float bufA[D], bufB[D], bufC[D];
    int seg = blockIdx.x;
    int t = threadIdx.x;

    float cnt = fmaxf(g_cnt[seg], 1.0f);
    float cv = g_sums[seg * D + t] / cnt;     // c_V
    bufA[t] = cv;
    __syncthreads();

    // --- V MLP ---
    float v = layer_dot(bufA, VW1, Vb1, t);
    bufB[t] = fmaxf(v, 0.0f);
    __syncthreads();
    v = layer_dot(bufB, VW2, Vb2, t);
    bufC[t] = fmaxf(v, 0.0f);
    __syncthreads();
    v = layer_dot(bufC, VW3, Vb3, t);
    float gV = 1.0f / (1.0f + expf(-v));
    g_gateV[seg * D + t] = gV;
    __syncthreads();

    // c_V2 = c_V * gate_V
    bufB[t] = cv * gV;
    __syncthreads();

    // --- E MLP ---
    v = layer_dot(bufB, EW1, Eb1, t);
    bufC[t] = fmaxf(v, 0.0f);
    __syncthreads();
    v = layer_dot(bufC, EW2, Eb2, t);
    bufA[t] = fmaxf(v, 0.0f);
    __syncthreads();
    v = layer_dot(bufA, EW3, Eb3, t);
    g_gateE[seg * D + t] = 1.0f / (1.0f + expf(-v));
}

// ---------------------------------------------------------------------------
// Node gating: out[i,:] = dst_na[i,:] * gate_V[batch_id[i],:]  (float4)
__global__ void gate_nodes_kernel(const float* __restrict__ x,
                                  const int* __restrict__ bid,
                                  float* __restrict__ out, int n4) {
    int i = blockIdx.x * blockDim.x + threadIdx.x;
    if (i >= n4) return;
    int row = i >> 5;           // 32 float4 per row (D=128)
    int c4 = i & 31;
    int s = __ldg(&bid[row]);
    float4 v = reinterpret_cast<const float4*>(x)[i];
    float4 g = *reinterpret_cast<const float4*>(&g_gateV[s * D + c4 * 4]);
    v.x *= g.x; v.y *= g.y; v.z *= g.z; v.w *= g.w;
    reinterpret_cast<float4*>(out)[i] = v;
}

// ---------------------------------------------------------------------------
// Edge gating: out[e,:] = ea[e,:] * gate_E[batch_id[edge_src[e]],:]  (float4)
__global__ void gate_edges_kernel(const float* __restrict__ ea,
                                  const int* __restrict__ edge_src,
                                  const int* __restrict__ bid,
                                  float* __restrict__ out, int n4) {
    int i = blockIdx.x * blockDim.x + threadIdx.x;
    if (i >= n4) return;
    int e = i >> 5;
    int c4 = i & 31;
    int src = __ldg(&edge_src[e]);
    int s = __ldg(&bid[src]);
    float4 v = reinterpret_cast<const float4*>(ea)[i];
    float4 g = *reinterpret_cast<const float4*>(&g_gateE[s * D + c4 * 4]);
    v.x *= g.x; v.y *= g.y; v.z *= g.z; v.w *= g.w;
    reinterpret_cast<float4*>(out)[i] = v;
}

// ---------------------------------------------------------------------------
extern "C" void kernel_launch(void* const* d_in, const int* in_sizes, int n_in,
                              void* d_out, int out_size) {
    const float* dst_na  = (const float*)d_in[0];
    const float* ea      = (const float*)d_in[1];
    const int*   eidx    = (const int*)d_in[2];   // [2, E], row 0 = src
    const int*   bid     = (const int*)d_in[3];
    const float* VW1 = (const float*)d_in[4];
    const float* Vb1 = (const float*)d_in[5];
    const float* VW2 = (const float*)d_in[6];
    const float* Vb2 = (const float*)d_in[7];
    const float* VW3 = (const float*)d_in[8];
    const float* Vb3 = (const float*)d_in[9];
    const float* EW1 = (const float*)d_in[10];
    const float* Eb1 = (const float*)d_in[11];
    const float* EW2 = (const float*)d_in[12];
    const float* Eb2 = (const float*)d_in[13];
    const float* EW3 = (const float*)d_in[14];
    const float* Eb3 = (const float*)d_in[15];

    int N = in_sizes[0] / D;
    int E = in_sizes[1] / D;
    float* out_nodes = (float*)d_out;
    float* out_edges = (float*)d_out + (size_t)N * D;

    zero_kernel<<<(SEGS * D + 255) / 256, 256>>>();

    int sum_blocks = (N + ROWS_PER_BLOCK - 1) / ROWS_PER_BLOCK;
    seg_sum_kernel<<<sum_blocks, D>>>(dst_na, bid, N);

    mlp_kernel<<<SEGS, D>>>(VW1, Vb1, VW2, Vb2, VW3, Vb3,
                            EW1, Eb1, EW2, Eb2, EW3, Eb3);

    int n4_nodes = N * (D / 4);
    gate_nodes_kernel<<<(n4_nodes + 255) / 256, 256>>>(dst_na, bid, out_nodes, n4_nodes);

    int n4_edges = E * (D / 4);
    gate_edges_kernel<<<(n4_edges + 255) / 256, 256>>>(ea, eidx, bid, out_edges, n4_edges);
}

// round 3
// speedup vs baseline: 1.1099x; 1.1099x over previous
#include <cuda_runtime.h>
#include <math.h>

#define D 128
#define SEGS 32
#define ROWS_PER_BLOCK 128
#define GROWS 64            // rows per gate block (64 rows * 32 float4 = 2048 f4 = 8/thread)

// Scratch (no allocations allowed) — zeroed every launch by zero_kernel.
__device__ __align__(16) float g_sums[SEGS * D];
__device__ float g_cnt[SEGS];
__device__ __align__(16) float g_gateV[SEGS * D];
__device__ __align__(16) float g_gateE[SEGS * D];

// ---------------------------------------------------------------------------
__global__ void zero_kernel() {
    int i = blockIdx.x * blockDim.x + threadIdx.x;
    if (i < SEGS * D) g_sums[i] = 0.0f;
    if (i < SEGS) g_cnt[i] = 0.0f;
}

// ---------------------------------------------------------------------------
// Segment sums over sorted batch_id. 128 threads/block, one column each.
// Fast path: block's rows all in one segment (common: ~3125 rows/segment)
// -> branch-free unrolled loop, loads batch well.
__global__ void seg_sum_kernel(const float* __restrict__ x,
                               const int* __restrict__ bid, int N) {
    int r0 = blockIdx.x * ROWS_PER_BLOCK;
    if (r0 >= N) return;
    int r1 = min(r0 + ROWS_PER_BLOCK, N);
    int t = threadIdx.x;

    int s0 = __ldg(&bid[r0]);
    int s1 = __ldg(&bid[r1 - 1]);

    if (s0 == s1) {
        float acc = 0.0f;
#pragma unroll 8
        for (int r = r0; r < r1; r++)
            acc += x[(size_t)r * D + t];
        atomicAdd(&g_sums[s0 * D + t], acc);
        if (t == 0) atomicAdd(&g_cnt[s0], (float)(r1 - r0));
    } else {
        float acc = 0.0f;
        float cnt = 0.0f;
        int cur = s0;
        for (int r = r0; r < r1; r++) {
            int s = __ldg(&bid[r]);
            if (s != cur) {
                atomicAdd(&g_sums[cur * D + t], acc);
                if (t == 0) atomicAdd(&g_cnt[cur], cnt);
                acc = 0.0f; cnt = 0.0f; cur = s;
            }
            acc += x[(size_t)r * D + t];
            cnt += 1.0f;
        }
        atomicAdd(&g_sums[cur * D + t], acc);
        if (t == 0) atomicAdd(&g_cnt[cur], cnt);
    }
}

// ---------------------------------------------------------------------------
// Tiny MLPs: 32 blocks (one per segment), 128 threads (one per feature).
// gate_V = sig(mlp_V(c_V)); c_V2 = c_V * gate_V (exact: gate constant per
// segment + mean linear); gate_E = sig(mlp_E(c_V2)).
__device__ __forceinline__ float layer_dot(const float* __restrict__ sx,
                                           const float* __restrict__ W,
                                           const float* __restrict__ b, int t) {
    float s = __ldg(&b[t]);
#pragma unroll 16
    for (int k = 0; k < D; k++)
        s = fmaf(sx[k], __ldg(&W[k * D + t]), s);
    return s;
}

__global__ void mlp_kernel(
    const float* __restrict__ VW1, const float* __restrict__ Vb1,
    const float* __restrict__ VW2, const float* __restrict__ Vb2,
    const float* __restrict__ VW3, const float* __restrict__ Vb3,
    const float* __restrict__ EW1, const float* __restrict__ Eb1,
    const float* __restrict__ EW2, const float* __restrict__ Eb2,
    const float* __restrict__ EW3, const float* __restrict__ Eb3) {
    __shared__ float bufA[D], bufB[D], bufC[D];
    int seg = blockIdx.x;
    int t = threadIdx.x;

    float cnt = fmaxf(g_cnt[seg], 1.0f);
    float cv = g_sums[seg * D + t] / cnt;     // c_V
    bufA[t] = cv;
    __syncthreads();

    // --- V MLP ---
    float v = layer_dot(bufA, VW1, Vb1, t);
    bufB[t] = fmaxf(v, 0.0f);
    __syncthreads();
    v = layer_dot(bufB, VW2, Vb2, t);
    bufC[t] = fmaxf(v, 0.0f);
    __syncthreads();
    v = layer_dot(bufC, VW3, Vb3, t);
    float gV = 1.0f / (1.0f + expf(-v));
    g_gateV[seg * D + t] = gV;
    __syncthreads();

    // c_V2 = c_V * gate_V
    bufB[t] = cv * gV;
    __syncthreads();

    // --- E MLP ---
    v = layer_dot(bufB, EW1, Eb1, t);
    bufC[t] = fmaxf(v, 0.0f);
    __syncthreads();
    v = layer_dot(bufC, EW2, Eb2, t);
    bufA[t] = fmaxf(v, 0.0f);
    __syncthreads();
    v = layer_dot(bufA, EW3, Eb3, t);
    g_gateE[seg * D + t] = 1.0f / (1.0f + expf(-v));
}

// ---------------------------------------------------------------------------
// Combined gating kernel. Blocks [0, nodeBlocks) gate nodes, the rest gate
// edges. Per block: 64 rows. Phase 1 — 64 threads resolve segment ids into
// smem (dependent chains run in parallel, once per row instead of x32).
// Phase 2 — unrolled float4 loop, 8 elems/thread, MLP=8.
__global__ void __launch_bounds__(256) gate_kernel(
    const float* __restrict__ x, const float* __restrict__ ea,
    const int* __restrict__ eidx, const int* __restrict__ bid,
    float* __restrict__ outN, float* __restrict__ outE,
    int N, int E, int nodeBlocks) {
    __shared__ int ssid[GROWS];
    int t = threadIdx.x;
    int b = blockIdx.x;

    if (b < nodeBlocks) {
        int r0 = b * GROWS;
        if (t < GROWS) {
            int r = r0 + t;
            ssid[t] = (r < N) ? __ldg(&bid[r]) : 0;
        }
        __syncthreads();
        const float4* src = (const float4*)x;
        float4* dst = (float4*)outN;
        long long base = (long long)r0 * 32;
#pragma unroll
        for (int it = 0; it < 8; it++) {
            int i = it * 256 + t;                 // 0..2047 within block
            int r = r0 + (i >> 5);
            if (r < N) {
                int s = ssid[i >> 5];
                float4 g = *(const float4*)&g_gateV[s * D + (i & 31) * 4];
                float4 v = src[base + i];
                v.x *= g.x; v.y *= g.y; v.z *= g.z; v.w *= g.w;
                dst[base + i] = v;
            }
        }
    } else {
        int r0 = (b - nodeBlocks) * GROWS;
        if (t < GROWS) {
            int r = r0 + t;
            ssid[t] = (r < E) ? __ldg(&bid[__ldg(&eidx[r])]) : 0;
        }
        __syncthreads();
        const float4* src = (const float4*)ea;
        float4* dst = (float4*)outE;
        long long base = (long long)r0 * 32;
#pragma unroll
        for (int it = 0; it < 8; it++) {
            int i = it * 256 + t;
            int r = r0 + (i >> 5);
            if (r < E) {
                int s = ssid[i >> 5];
                float4 g = *(const float4*)&g_gateE[s * D + (i & 31) * 4];
                float4 v = src[base + i];
                v.x *= g.x; v.y *= g.y; v.z *= g.z; v.w *= g.w;
                dst[base + i] = v;
            }
        }
    }
}

// ---------------------------------------------------------------------------
extern "C" void kernel_launch(void* const* d_in, const int* in_sizes, int n_in,
                              void* d_out, int out_size) {
    const float* dst_na  = (const float*)d_in[0];
    const float* ea      = (const float*)d_in[1];
    const int*   eidx    = (const int*)d_in[2];   // [2, E], row 0 = src
    const int*   bid     = (const int*)d_in[3];
    const float* VW1 = (const float*)d_in[4];
    const float* Vb1 = (const float*)d_in[5];
    const float* VW2 = (const float*)d_in[6];
    const float* Vb2 = (const float*)d_in[7];
    const float* VW3 = (const float*)d_in[8];
    const float* Vb3 = (const float*)d_in[9];
    const float* EW1 = (const float*)d_in[10];
    const float* Eb1 = (const float*)d_in[11];
    const float* EW2 = (const float*)d_in[12];
    const float* Eb2 = (const float*)d_in[13];
    const float* EW3 = (const float*)d_in[14];
    const float* Eb3 = (const float*)d_in[15];

    int N = in_sizes[0] / D;
    int E = in_sizes[1] / D;
    float* out_nodes = (float*)d_out;
    float* out_edges = (float*)d_out + (size_t)N * D;

    zero_kernel<<<(SEGS * D + 255) / 256, 256>>>();

    int sum_blocks = (N + ROWS_PER_BLOCK - 1) / ROWS_PER_BLOCK;
    seg_sum_kernel<<<sum_blocks, D>>>(dst_na, bid, N);

    mlp_kernel<<<SEGS, D>>>(VW1, Vb1, VW2, Vb2, VW3, Vb3,
                            EW1, Eb1, EW2, Eb2, EW3, Eb3);

    int nodeBlocks = (N + GROWS - 1) / GROWS;
    int edgeBlocks = (E + GROWS - 1) / GROWS;
    gate_kernel<<<nodeBlocks + edgeBlocks, 256>>>(
        dst_na, ea, eidx, bid, out_nodes, out_edges, N, E, nodeBlocks);
}

// round 4
// speedup vs baseline: 1.2821x; 1.1552x over previous
#include <cuda_runtime.h>
#include <math.h>

#define D 128
#define SEGS 32
#define ROWS_PER_BLOCK 128
#define GROWS 64            // rows per gate block

// Scratch — zero-initialized at module load; mlp_kernel re-zeroes at its end
// so every launch (correctness, capture, replay) starts clean.
__device__ __align__(16) float g_sums[SEGS * D];
__device__ float g_cnt[SEGS];
__device__ __align__(16) float g_gateV[SEGS * D];
__device__ __align__(16) float g_gateE[SEGS * D];

// ---------------------------------------------------------------------------
// Segment sums over sorted batch_id. 128 threads = 4 warps.
// Fast path (block fully inside one segment, ~96% of blocks): each warp
// accumulates a float4 over its 32-row chunk, cross-warp reduce in smem,
// 128 atomics per block.
__global__ void __launch_bounds__(128) seg_sum_kernel(
    const float* __restrict__ x, const int* __restrict__ bid, int N) {
    int r0 = blockIdx.x * ROWS_PER_BLOCK;
    if (r0 >= N) return;
    int r1 = min(r0 + ROWS_PER_BLOCK, N);
    int t = threadIdx.x;

    int s0 = __ldg(&bid[r0]);
    int s1 = __ldg(&bid[r1 - 1]);

    if (s0 == s1) {
        __shared__ float sred[4][D];
        int w = t >> 5, l = t & 31;
        const float4* xf4 = (const float4*)x;   // 32 float4 per row
        float4 acc = make_float4(0.f, 0.f, 0.f, 0.f);
        // warp w handles rows r0+w, r0+w+4, ... (interleaved, tail-safe)
        for (int r = r0 + w; r < r1; r += 4) {
            float4 v = xf4[(size_t)r * 32 + l];
            acc.x += v.x; acc.y += v.y; acc.z += v.z; acc.w += v.w;
        }
        *(float4*)&sred[w][l * 4] = acc;
        __syncthreads();
        float s = sred[0][t] + sred[1][t] + sred[2][t] + sred[3][t];
        atomicAdd(&g_sums[s0 * D + t], s);
        if (t == 0) atomicAdd(&g_cnt[s0], (float)(r1 - r0));
    } else {
        // slow path: per-row scalar with boundary flushes (rare blocks)
        float acc = 0.0f, cnt = 0.0f;
        int cur = s0;
        for (int r = r0; r < r1; r++) {
            int s = __ldg(&bid[r]);
            if (s != cur) {
                atomicAdd(&g_sums[cur * D + t], acc);
                if (t == 0) atomicAdd(&g_cnt[cur], cnt);
                acc = 0.0f; cnt = 0.0f; cur = s;
            }
            acc += x[(size_t)r * D + t];
            cnt += 1.0f;
        }
        atomicAdd(&g_sums[cur * D + t], acc);
        if (t == 0) atomicAdd(&g_cnt[cur], cnt);
    }
}

// ---------------------------------------------------------------------------
// MLPs: 32 blocks (one per segment) x 512 threads. Each output's 128-term dot
// is split 4 ways across thread-groups (32 loads + 32 FMAs each), smem reduce.
// gate_V = sig(mlpV(c_V)); c_V2 = c_V*gate_V (exact: gate const per segment,
// mean linear); gate_E = sig(mlpE(c_V2)). Re-zeroes scratch at the end.
__device__ __forceinline__ void mlp_layer(
    const float* __restrict__ sin, float* __restrict__ sout,
    const float* __restrict__ W, const float* __restrict__ b,
    float (*sred)[D], int t128, int part, bool do_relu) {
    float p = 0.0f;
    const float* Wp = W + (part * 32) * D + t128;
    const float* xp = sin + part * 32;
#pragma unroll
    for (int k = 0; k < 32; k++)
        p = fmaf(xp[k], __ldg(&Wp[k * D]), p);
    sred[part][t128] = p;
    __syncthreads();
    if (part == 0) {
        float v = sred[0][t128] + sred[1][t128] + sred[2][t128] + sred[3][t128]
                + __ldg(&b[t128]);
        sout[t128] = do_relu ? fmaxf(v, 0.0f) : v;
    }
    __syncthreads();
}

__global__ void __launch_bounds__(512) mlp_kernel(
    const float* __restrict__ VW1, const float* __restrict__ Vb1,
    const float* __restrict__ VW2, const float* __restrict__ Vb2,
    const float* __restrict__ VW3, const float* __restrict__ Vb3,
    const float* __restrict__ EW1, const float* __restrict__ Eb1,
    const float* __restrict__ EW2, const float* __restrict__ Eb2,
    const float* __restrict__ EW3, const float* __restrict__ Eb3) {
    __shared__ float scv[D], bufA[D], bufB[D];
    __shared__ float sred[4][D];
    int seg = blockIdx.x;
    int t = threadIdx.x;
    int t128 = t & 127;
    int part = t >> 7;

    if (t < D) {
        float cnt = fmaxf(g_cnt[seg], 1.0f);
        float cv = g_sums[seg * D + t] / cnt;
        scv[t] = cv;
    }
    __syncthreads();

    // --- V MLP ---
    mlp_layer(scv,  bufA, VW1, Vb1, sred, t128, part, true);
    mlp_layer(bufA, bufB, VW2, Vb2, sred, t128, part, true);
    mlp_layer(bufB, bufA, VW3, Vb3, sred, t128, part, false);
    if (t < D) {
        float gV = 1.0f / (1.0f + expf(-bufA[t]));
        g_gateV[seg * D + t] = gV;
        bufB[t] = scv[t] * gV;     // c_V2
    }
    __syncthreads();

    // --- E MLP ---
    mlp_layer(bufB, bufA, EW1, Eb1, sred, t128, part, true);
    mlp_layer(bufA, bufB, EW2, Eb2, sred, t128, part, true);
    mlp_layer(bufB, bufA, EW3, Eb3, sred, t128, part, false);
    if (t < D) {
        g_gateE[seg * D + t] = 1.0f / (1.0f + expf(-bufA[t]));
        // restore scratch for the next launch (zero-invariant at entry)
        g_sums[seg * D + t] = 0.0f;
        if (t == 0) g_cnt[seg] = 0.0f;
    }
}

// ---------------------------------------------------------------------------
// Combined gating. Blocks [0, nodeBlocks) gate nodes (dst_na L2-hot from
// seg_sum — plain loads), the rest gate edges (pure streaming — __ldcs/__stcs
// to avoid thrashing L2). 64 rows/block; segment ids staged in smem.
__global__ void __launch_bounds__(256) gate_kernel(
    const float* __restrict__ x, const float* __restrict__ ea,
    const int* __restrict__ eidx, const int* __restrict__ bid,
    float* __restrict__ outN, float* __restrict__ outE,
    int N, int E, int nodeBlocks) {
    __shared__ int ssid[GROWS];
    int t = threadIdx.x;
    int b = blockIdx.x;

    if (b < nodeBlocks) {
        int r0 = b * GROWS;
        if (t < GROWS) {
            int r = r0 + t;
            ssid[t] = (r < N) ? __ldg(&bid[r]) : 0;
        }
        __syncthreads();
        const float4* src = (const float4*)x;
        float4* dst = (float4*)outN;
        long long base = (long long)r0 * 32;
#pragma unroll
        for (int it = 0; it < 8; it++) {
            int i = it * 256 + t;
            int r = r0 + (i >> 5);
            if (r < N) {
                int s = ssid[i >> 5];
                float4 g = *(const float4*)&g_gateV[s * D + (i & 31) * 4];
                float4 v = src[base + i];
                v.x *= g.x; v.y *= g.y; v.z *= g.z; v.w *= g.w;
                __stcs(&dst[base + i], v);
            }
        }
    } else {
        int r0 = (b - nodeBlocks) * GROWS;
        if (t < GROWS) {
            int r = r0 + t;
            ssid[t] = (r < E) ? __ldg(&bid[__ldg(&eidx[r])]) : 0;
        }
        __syncthreads();
        const float4* src = (const float4*)ea;
        float4* dst = (float4*)outE;
        long long base = (long long)r0 * 32;
#pragma unroll
        for (int it = 0; it < 8; it++) {
            int i = it * 256 + t;
            int r = r0 + (i >> 5);
            if (r < E) {
                int s = ssid[i >> 5];
                float4 g = *(const float4*)&g_gateE[s * D + (i & 31) * 4];
                float4 v = __ldcs(&src[base + i]);
                v.x *= g.x; v.y *= g.y; v.z *= g.z; v.w *= g.w;
                __stcs(&dst[base + i], v);
            }
        }
    }
}

// ---------------------------------------------------------------------------
extern "C" void kernel_launch(void* const* d_in, const int* in_sizes, int n_in,
                              void* d_out, int out_size) {
    const float* dst_na  = (const float*)d_in[0];
    const float* ea      = (const float*)d_in[1];
    const int*   eidx    = (const int*)d_in[2];   // [2, E], row 0 = src
    const int*   bid     = (const int*)d_in[3];
    const float* VW1 = (const float*)d_in[4];
    const float* Vb1 = (const float*)d_in[5];
    const float* VW2 = (const float*)d_in[6];
    const float* Vb2 = (const float*)d_in[7];
    const float* VW3 = (const float*)d_in[8];
    const float* Vb3 = (const float*)d_in[9];
    const float* EW1 = (const float*)d_in[10];
    const float* Eb1 = (const float*)d_in[11];
    const float* EW2 = (const float*)d_in[12];
    const float* Eb2 = (const float*)d_in[13];
    const float* EW3 = (const float*)d_in[14];
    const float* Eb3 = (const float*)d_in[15];

    int N = in_sizes[0] / D;
    int E = in_sizes[1] / D;
    float* out_nodes = (float*)d_out;
    float* out_edges = (float*)d_out + (size_t)N * D;

    int sum_blocks = (N + ROWS_PER_BLOCK - 1) / ROWS_PER_BLOCK;
    seg_sum_kernel<<<sum_blocks, 128>>>(dst_na, bid, N);

    mlp_kernel<<<SEGS, 512>>>(VW1, Vb1, VW2, Vb2, VW3, Vb3,
                              EW1, Eb1, EW2, Eb2, EW3, Eb3);

    int nodeBlocks = (N + GROWS - 1) / GROWS;
    int edgeBlocks = (E + GROWS - 1) / GROWS;
    gate_kernel<<<nodeBlocks + edgeBlocks, 256>>>(
        dst_na, ea, eidx, bid, out_nodes, out_edges, N, E, nodeBlocks);
}